// round 8
// baseline (speedup 1.0000x reference)
#include <cuda_runtime.h>

#define B_   8
#define C_   64
#define H_   128
#define W_   128
#define O_   16      // C / RED
#define G_   32      // total groups
#define GQ_  8       // groups per CTA (quarter)
#define GC_  2       // channels per group
#define KK_  9       // 3x3
#define KP_  10      // padded kernel stride (u64 units) for 16B alignment

typedef unsigned long long u64;

// scratch for t = PReLU(w1 @ x + b1): [B][O][H][W]
__device__ float t_scratch[B_ * O_ * H_ * W_];

__device__ __forceinline__ u64 pack2(float lo, float hi) {
    u64 r;
    asm("mov.b64 %0, {%1,%2};" : "=l"(r) : "f"(lo), "f"(hi));
    return r;
}
__device__ __forceinline__ void unpack2(u64 v, float& lo, float& hi) {
    asm("mov.b64 {%0,%1}, %2;" : "=f"(lo), "=f"(hi) : "l"(v));
}
// d = a*b + d, packed f32x2 (Blackwell FFMA2)
__device__ __forceinline__ void fma2(u64& d, u64 a, u64 b) {
    asm("fma.rn.f32x2 %0, %1, %2, %0;" : "+l"(d) : "l"(a), "l"(b));
}
__device__ __forceinline__ u64 add2(u64 a, u64 b) {
    u64 r;
    asm("add.rn.f32x2 %0, %1, %2;" : "=l"(r) : "l"(a), "l"(b));
    return r;
}

// ---------------- Kernel A: t = PReLU(w1 @ x + b1) ----------------
__global__ void __launch_bounds__(64, 16) gen_t_kernel(
    const float* __restrict__ x,
    const float* __restrict__ w1,
    const float* __restrict__ b1,
    const float* __restrict__ pa)
{
    __shared__ float2 s_w1[C_ * O_];   // duplicated (s,s): 8 KB

    const int tid = threadIdx.x;
    for (int i = tid; i < C_ * O_; i += 64) {
        int c = i >> 4, o = i & 15;
        float v = w1[o * C_ + c];
        s_w1[i] = make_float2(v, v);
    }
    __syncthreads();

    const int b = blockIdx.z;
    const int h = blockIdx.y;
    const int w = tid * 2;            // pixel pair
    const float alpha = pa[0];

    const float* xc = x + (size_t)b * C_ * H_ * W_ + h * W_ + w;

    u64 t2[O_];
#pragma unroll
    for (int o = 0; o < O_; o++) {
        float bv = b1[o];
        t2[o] = pack2(bv, bv);
    }

#pragma unroll 4
    for (int c = 0; c < C_; c++) {
        float2 xv = *reinterpret_cast<const float2*>(xc + c * (H_ * W_));
        u64 xp = pack2(xv.x, xv.y);
        const ulonglong2* wv = reinterpret_cast<const ulonglong2*>(&s_w1[c * O_]);
#pragma unroll
        for (int o2 = 0; o2 < 8; o2++) {
            ulonglong2 wpair = wv[o2];   // LDS.128: two duplicated scalars
            fma2(t2[2 * o2 + 0], xp, wpair.x);
            fma2(t2[2 * o2 + 1], xp, wpair.y);
        }
    }

    // PReLU + store as packed pairs (bit-identical to float2 store)
    u64* tout = reinterpret_cast<u64*>(t_scratch + ((size_t)b * O_ * H_ + h) * W_ + w);
#pragma unroll
    for (int o = 0; o < O_; o++) {
        float a, bb;
        unpack2(t2[o], a, bb);
        a  = (a  >= 0.f) ? a  : alpha * a;
        bb = (bb >= 0.f) ? bb : alpha * bb;
        tout[o * (H_ * W_ / 2)] = pack2(a, bb);
    }
}

// ---------------- Kernel B: per-pixel kernels + 3x3 gather ----------------
__global__ void __launch_bounds__(128, 6) involution_apply_kernel(
    const float* __restrict__ x,
    const float* __restrict__ w2,
    const float* __restrict__ b2,
    float* __restrict__ out)
{
    // Duplicated-scalar (s,s) weight tables; quarter of the groups
    __shared__ float2 s_w2[GQ_ * O_ * KP_];  // [gl][o][kk pad10] : 10 KB
    __shared__ float2 s_b2[GQ_ * KP_];       // [gl][kk pad10]    : 640 B

    const int tid = threadIdx.y * 64 + threadIdx.x;
    const int g0  = blockIdx.x * GQ_;        // group-quarter base

    for (int i = tid; i < GQ_ * O_ * KK_; i += 128) {
        int kk = i % KK_;
        int rest = i / KK_;
        int o  = rest & 15;
        int gl = rest >> 4;
        float v = w2[((g0 + gl) * KK_ + kk) * O_ + o];
        s_w2[(gl * O_ + o) * KP_ + kk] = make_float2(v, v);
    }
    for (int i = tid; i < GQ_ * KP_; i += 128) {
        int gl = i / KP_, kk = i % KP_;
        float v = (kk < KK_) ? b2[(g0 + gl) * KK_ + kk] : 0.f;
        s_b2[i] = make_float2(v, v);
    }
    __syncthreads();

    const int b = blockIdx.z;
    const int h = blockIdx.y * 2 + threadIdx.y;
    const int w = threadIdx.x * 2;          // pixel pair (w, w+1)

    const float* xb = x + (size_t)b * C_ * H_ * W_;

    // Load t for this pixel pair: naturally packed (t[px0], t[px1]) — no dup,
    // no packs, no LDS in the o-loop.
    u64 tv[O_];
    {
        const u64* tp = reinterpret_cast<const u64*>(
            t_scratch + ((size_t)b * O_ * H_ + h) * W_ + w);
#pragma unroll
        for (int o = 0; o < O_; o++) tv[o] = tp[o * (H_ * W_ / 2)];
    }

    const bool hv0 = (h > 0);
    const bool hv2 = (h < H_ - 1);
    const bool wv0 = (w > 0);
    const bool wv2 = (w + 2 < W_);

    float* outp = out + (size_t)b * C_ * H_ * W_ + h * W_ + w;
    const u64* s_b2u = reinterpret_cast<const u64*>(s_b2);

#pragma unroll 1
    for (int gl = 0; gl < GQ_; gl++) {
        u64 wk[KK_];
#pragma unroll
        for (int kk = 0; kk < KK_; kk++) wk[kk] = s_b2u[gl * KP_ + kk];

#pragma unroll
        for (int o = 0; o < O_; o++) {
            u64 t_ = tv[o];
            const u64* wrow =
                reinterpret_cast<const u64*>(&s_w2[(gl * O_ + o) * KP_]);
#pragma unroll
            for (int kk = 0; kk < KK_; kk++) fma2(wk[kk], t_, wrow[kk]);
        }

#pragma unroll
        for (int cc = 0; cc < GC_; cc++) {
            const int c = (g0 + gl) * GC_ + cc;
            const float* xr = xb + (size_t)c * (H_ * W_) + h * W_ + w;
            u64 accA = 0ULL, accB = 0ULL;  // two chains for ILP
#pragma unroll
            for (int di = 0; di < 3; di++) {
                const bool hv = (di == 0) ? hv0 : ((di == 2) ? hv2 : true);
                const float* row = xr + (di - 1) * W_;
                float L = (hv && wv0) ? row[-1] : 0.f;
                u64  m  = hv ? *reinterpret_cast<const u64*>(row) : 0ULL;
                float R = (hv && wv2) ? row[2] : 0.f;
                float m0, m1;
                unpack2(m, m0, m1);
                u64& acc = (di == 1) ? accB : accA;
                fma2(acc, wk[3 * di + 0], pack2(L, m0));
                fma2(acc, wk[3 * di + 1], m);          // center taps: packed as-is
                fma2(acc, wk[3 * di + 2], pack2(m1, R));
            }
            u64 acc = add2(accA, accB);
            float a0, a1;
            unpack2(acc, a0, a1);
            *reinterpret_cast<float2*>(outp + (size_t)c * (H_ * W_)) =
                make_float2(a0, a1);
        }
    }
}

extern "C" void kernel_launch(void* const* d_in, const int* in_sizes, int n_in,
                              void* d_out, int out_size)
{
    (void)in_sizes; (void)n_in; (void)out_size;
    const float* x  = (const float*)d_in[0];
    const float* w1 = (const float*)d_in[1];
    const float* b1 = (const float*)d_in[2];
    const float* pa = (const float*)d_in[3];
    const float* w2 = (const float*)d_in[4];
    const float* b2 = (const float*)d_in[5];
    float* out = (float*)d_out;

    // Kernel A: 1024 small CTAs (2 warps each) — high residency, short
    dim3 blockA(64, 1, 1);
    dim3 gridA(1, H_, B_);
    gen_t_kernel<<<gridA, blockA>>>(x, w1, b1, pa);

    // Kernel B: 2048 CTAs, 4-way group split, 6 CTAs/SM target
    dim3 blockB(64, 2, 1);
    dim3 gridB(4, H_ / 2, B_);
    involution_apply_kernel<<<gridB, blockB>>>(x, w2, b2, out);
}

// round 9
// speedup vs baseline: 1.0587x; 1.0587x over previous
#include <cuda_runtime.h>

#define B_   8
#define C_   64
#define H_   128
#define W_   128
#define O_   16      // C / RED
#define G_   32      // total groups
#define GQ_  8       // groups per CTA (quarter)
#define GC_  2       // channels per group
#define KK_  9       // 3x3
#define KP_  10      // padded kernel stride (u64 units) for 16B alignment

typedef unsigned long long u64;

// scratch for t = PReLU(w1 @ x + b1): [B][O][H][W]
__device__ float t_scratch[B_ * O_ * H_ * W_];

__device__ __forceinline__ u64 pack2(float lo, float hi) {
    u64 r;
    asm("mov.b64 %0, {%1,%2};" : "=l"(r) : "f"(lo), "f"(hi));
    return r;
}
__device__ __forceinline__ void unpack2(u64 v, float& lo, float& hi) {
    asm("mov.b64 {%0,%1}, %2;" : "=f"(lo), "=f"(hi) : "l"(v));
}
// d = a*b + d, packed f32x2 (Blackwell FFMA2)
__device__ __forceinline__ void fma2(u64& d, u64 a, u64 b) {
    asm("fma.rn.f32x2 %0, %1, %2, %0;" : "+l"(d) : "l"(a), "l"(b));
}
__device__ __forceinline__ u64 add2(u64 a, u64 b) {
    u64 r;
    asm("add.rn.f32x2 %0, %1, %2;" : "=l"(r) : "l"(a), "l"(b));
    return r;
}
// explicit 128-bit shared load (forces LDS.128)
__device__ __forceinline__ ulonglong2 lds128(const ulonglong2* p) {
    ulonglong2 v;
    asm("ld.shared.v2.u64 {%0,%1}, [%2];"
        : "=l"(v.x), "=l"(v.y) : "l"(p));
    return v;
}

// ---------------- Kernel A: t = PReLU(w1 @ x + b1) ----------------
__global__ void __launch_bounds__(64, 16) gen_t_kernel(
    const float* __restrict__ x,
    const float* __restrict__ w1,
    const float* __restrict__ b1,
    const float* __restrict__ pa)
{
    __shared__ float2 s_w1[C_ * O_];   // duplicated (s,s): 8 KB

    const int tid = threadIdx.x;
    for (int i = tid; i < C_ * O_; i += 64) {
        int c = i >> 4, o = i & 15;
        float v = w1[o * C_ + c];
        s_w1[i] = make_float2(v, v);
    }
    __syncthreads();

    const int b = blockIdx.z;
    const int h = blockIdx.y;
    const int w = tid * 2;            // pixel pair
    const float alpha = pa[0];

    const float* xc = x + (size_t)b * C_ * H_ * W_ + h * W_ + w;

    u64 t2[O_];
#pragma unroll
    for (int o = 0; o < O_; o++) {
        float bv = b1[o];
        t2[o] = pack2(bv, bv);
    }

#pragma unroll 4
    for (int c = 0; c < C_; c++) {
        float2 xv = *reinterpret_cast<const float2*>(xc + c * (H_ * W_));
        u64 xp = pack2(xv.x, xv.y);
        const ulonglong2* wv = reinterpret_cast<const ulonglong2*>(&s_w1[c * O_]);
#pragma unroll
        for (int o2 = 0; o2 < 8; o2++) {
            ulonglong2 wpair = lds128(wv + o2);   // LDS.128
            fma2(t2[2 * o2 + 0], xp, wpair.x);
            fma2(t2[2 * o2 + 1], xp, wpair.y);
        }
    }

    // PReLU + store as packed pairs
    u64* tout = reinterpret_cast<u64*>(t_scratch + ((size_t)b * O_ * H_ + h) * W_ + w);
#pragma unroll
    for (int o = 0; o < O_; o++) {
        float a, bb;
        unpack2(t2[o], a, bb);
        a  = (a  >= 0.f) ? a  : alpha * a;
        bb = (bb >= 0.f) ? bb : alpha * bb;
        tout[o * (H_ * W_ / 2)] = pack2(a, bb);
    }
}

// ---------------- Kernel B: per-pixel kernels + 3x3 gather ----------------
__global__ void __launch_bounds__(128, 6) involution_apply_kernel(
    const float* __restrict__ x,
    const float* __restrict__ w2,
    const float* __restrict__ b2,
    float* __restrict__ out)
{
    // Duplicated-scalar (s,s) weight tables; quarter of the groups
    __shared__ float2 s_w2[GQ_ * O_ * KP_];  // [gl][o][kk pad10] : 10 KB
    __shared__ float2 s_b2[GQ_ * KP_];       // [gl][kk pad10]    : 640 B

    const int tid = threadIdx.y * 64 + threadIdx.x;
    const int g0  = blockIdx.x * GQ_;        // group-quarter base

    for (int i = tid; i < GQ_ * O_ * KK_; i += 128) {
        int kk = i % KK_;
        int rest = i / KK_;
        int o  = rest & 15;
        int gl = rest >> 4;
        float v = w2[((g0 + gl) * KK_ + kk) * O_ + o];
        s_w2[(gl * O_ + o) * KP_ + kk] = make_float2(v, v);
    }
    for (int i = tid; i < GQ_ * KP_; i += 128) {
        int gl = i / KP_, kk = i % KP_;
        float v = (kk < KK_) ? b2[(g0 + gl) * KK_ + kk] : 0.f;
        s_b2[i] = make_float2(v, v);
    }
    __syncthreads();

    const int b = blockIdx.z;
    const int h = blockIdx.y * 2 + threadIdx.y;
    const int w = threadIdx.x * 2;          // pixel pair (w, w+1)

    const float* xb = x + (size_t)b * C_ * H_ * W_;

    // Load t for this pixel pair: naturally packed (t[px0], t[px1])
    u64 tv[O_];
    {
        const u64* tp = reinterpret_cast<const u64*>(
            t_scratch + ((size_t)b * O_ * H_ + h) * W_ + w);
#pragma unroll
        for (int o = 0; o < O_; o++) tv[o] = tp[o * (H_ * W_ / 2)];
    }

    const bool hv0 = (h > 0);
    const bool hv2 = (h < H_ - 1);
    const bool wv0 = (w > 0);
    const bool wv2 = (w + 2 < W_);

    float* outp = out + (size_t)b * C_ * H_ * W_ + h * W_ + w;

#pragma unroll 1
    for (int gl = 0; gl < GQ_; gl++) {
        u64 wk[KK_];
        {
            // bias row: KP_=10 u64, 16B aligned -> 4x LDS.128 + 1 LDS.64
            const ulonglong2* brow = reinterpret_cast<const ulonglong2*>(
                reinterpret_cast<const u64*>(s_b2) + gl * KP_);
#pragma unroll
            for (int kp = 0; kp < 4; kp++) {
                ulonglong2 v = lds128(brow + kp);
                wk[2 * kp + 0] = v.x;
                wk[2 * kp + 1] = v.y;
            }
            wk[8] = reinterpret_cast<const u64*>(s_b2)[gl * KP_ + 8];
        }

#pragma unroll
        for (int o = 0; o < O_; o++) {
            u64 t_ = tv[o];
            const u64* wrow =
                reinterpret_cast<const u64*>(&s_w2[(gl * O_ + o) * KP_]);
            const ulonglong2* wrow2 = reinterpret_cast<const ulonglong2*>(wrow);
#pragma unroll
            for (int kp = 0; kp < 4; kp++) {
                ulonglong2 v = lds128(wrow2 + kp);   // LDS.128: 2 weights
                fma2(wk[2 * kp + 0], t_, v.x);
                fma2(wk[2 * kp + 1], t_, v.y);
            }
            fma2(wk[8], t_, wrow[8]);
        }

#pragma unroll
        for (int cc = 0; cc < GC_; cc++) {
            const int c = (g0 + gl) * GC_ + cc;
            const float* xr = xb + (size_t)c * (H_ * W_) + h * W_ + w;
            u64 accA = 0ULL, accB = 0ULL;  // two chains for ILP
#pragma unroll
            for (int di = 0; di < 3; di++) {
                const bool hv = (di == 0) ? hv0 : ((di == 2) ? hv2 : true);
                const float* row = xr + (di - 1) * W_;
                float L = (hv && wv0) ? row[-1] : 0.f;
                u64  m  = hv ? *reinterpret_cast<const u64*>(row) : 0ULL;
                float R = (hv && wv2) ? row[2] : 0.f;
                float m0, m1;
                unpack2(m, m0, m1);
                u64& acc = (di == 1) ? accB : accA;
                fma2(acc, wk[3 * di + 0], pack2(L, m0));
                fma2(acc, wk[3 * di + 1], m);          // center taps packed as-is
                fma2(acc, wk[3 * di + 2], pack2(m1, R));
            }
            u64 acc = add2(accA, accB);
            float a0, a1;
            unpack2(acc, a0, a1);
            *reinterpret_cast<float2*>(outp + (size_t)c * (H_ * W_)) =
                make_float2(a0, a1);
        }
    }
}

extern "C" void kernel_launch(void* const* d_in, const int* in_sizes, int n_in,
                              void* d_out, int out_size)
{
    (void)in_sizes; (void)n_in; (void)out_size;
    const float* x  = (const float*)d_in[0];
    const float* w1 = (const float*)d_in[1];
    const float* b1 = (const float*)d_in[2];
    const float* pa = (const float*)d_in[3];
    const float* w2 = (const float*)d_in[4];
    const float* b2 = (const float*)d_in[5];
    float* out = (float*)d_out;

    // Kernel A: 1024 small CTAs (2 warps each)
    dim3 blockA(64, 1, 1);
    dim3 gridA(1, H_, B_);
    gen_t_kernel<<<gridA, blockA>>>(x, w1, b1, pa);

    // Kernel B: 2048 CTAs, 4-way group split
    dim3 blockB(64, 2, 1);
    dim3 gridB(4, H_ / 2, B_);
    involution_apply_kernel<<<gridB, blockB>>>(x, w2, b2, out);
}

// round 10
// speedup vs baseline: 1.3791x; 1.3027x over previous
#include <cuda_runtime.h>

#define B_   8
#define C_   64
#define H_   128
#define W_   128
#define O_   16      // C / RED
#define G_   32      // total groups
#define GQ_  8       // groups per CTA (quarter)
#define GC_  2       // channels per group
#define KK_  9       // 3x3
#define KP_  10      // padded kernel stride (u64 units) for 16B alignment

typedef unsigned long long u64;

// scratch for t = PReLU(w1 @ x + b1): [B][O][H][W]
__device__ float t_scratch[B_ * O_ * H_ * W_];

__device__ __forceinline__ u64 pack2(float lo, float hi) {
    u64 r;
    asm("mov.b64 %0, {%1,%2};" : "=l"(r) : "f"(lo), "f"(hi));
    return r;
}
__device__ __forceinline__ void unpack2(u64 v, float& lo, float& hi) {
    asm("mov.b64 {%0,%1}, %2;" : "=f"(lo), "=f"(hi) : "l"(v));
}
// d = a*b + d, packed f32x2 (Blackwell FFMA2)
__device__ __forceinline__ void fma2(u64& d, u64 a, u64 b) {
    asm("fma.rn.f32x2 %0, %1, %2, %0;" : "+l"(d) : "l"(a), "l"(b));
}
__device__ __forceinline__ u64 add2(u64 a, u64 b) {
    u64 r;
    asm("add.rn.f32x2 %0, %1, %2;" : "=l"(r) : "l"(a), "l"(b));
    return r;
}
// explicit 128-bit shared load (forces LDS.128)
__device__ __forceinline__ ulonglong2 lds128(const ulonglong2* p) {
    ulonglong2 v;
    asm("ld.shared.v2.u64 {%0,%1}, [%2];"
        : "=l"(v.x), "=l"(v.y) : "l"(p));
    return v;
}

// ---------------- Kernel A: t = PReLU(w1 @ x + b1) ----------------
__global__ void __launch_bounds__(64, 16) gen_t_kernel(
    const float* __restrict__ x,
    const float* __restrict__ w1,
    const float* __restrict__ b1,
    const float* __restrict__ pa)
{
    __shared__ float2 s_w1[C_ * O_];   // duplicated (s,s): 8 KB

    const int tid = threadIdx.x;
    for (int i = tid; i < C_ * O_; i += 64) {
        int c = i >> 4, o = i & 15;
        float v = w1[o * C_ + c];
        s_w1[i] = make_float2(v, v);
    }
    __syncthreads();

    const int b = blockIdx.z;
    const int h = blockIdx.y;
    const int w = tid * 2;            // pixel pair
    const float alpha = pa[0];

    const float* xc = x + (size_t)b * C_ * H_ * W_ + h * W_ + w;

    u64 t2[O_];
#pragma unroll
    for (int o = 0; o < O_; o++) {
        float bv = b1[o];
        t2[o] = pack2(bv, bv);
    }

#pragma unroll 4
    for (int c = 0; c < C_; c++) {
        float2 xv = *reinterpret_cast<const float2*>(xc + c * (H_ * W_));
        u64 xp = pack2(xv.x, xv.y);
        const ulonglong2* wv = reinterpret_cast<const ulonglong2*>(&s_w1[c * O_]);
#pragma unroll
        for (int o2 = 0; o2 < 8; o2++) {
            ulonglong2 wpair = lds128(wv + o2);   // LDS.128
            fma2(t2[2 * o2 + 0], xp, wpair.x);
            fma2(t2[2 * o2 + 1], xp, wpair.y);
        }
    }

    // PReLU + store as packed pairs
    u64* tout = reinterpret_cast<u64*>(t_scratch + ((size_t)b * O_ * H_ + h) * W_ + w);
#pragma unroll
    for (int o = 0; o < O_; o++) {
        float a, bb;
        unpack2(t2[o], a, bb);
        a  = (a  >= 0.f) ? a  : alpha * a;
        bb = (bb >= 0.f) ? bb : alpha * bb;
        tout[o * (H_ * W_ / 2)] = pack2(a, bb);
    }
}

// ------- Kernel B: per-pixel kernels + 3x3 gather, 4 px/thread -------
__global__ void __launch_bounds__(128, 4) involution_apply_kernel(
    const float* __restrict__ x,
    const float* __restrict__ w2,
    const float* __restrict__ b2,
    float* __restrict__ out)
{
    // Duplicated-scalar (s,s) weight tables; quarter of the groups
    __shared__ float2 s_w2[GQ_ * O_ * KP_];  // [gl][o][kk pad10] : 10 KB
    __shared__ float2 s_b2[GQ_ * KP_];       // [gl][kk pad10]    : 640 B

    const int tid = threadIdx.y * 32 + threadIdx.x;
    const int g0  = blockIdx.x * GQ_;        // group-quarter base

    for (int i = tid; i < GQ_ * O_ * KK_; i += 128) {
        int kk = i % KK_;
        int rest = i / KK_;
        int o  = rest & 15;
        int gl = rest >> 4;
        float v = w2[((g0 + gl) * KK_ + kk) * O_ + o];
        s_w2[(gl * O_ + o) * KP_ + kk] = make_float2(v, v);
    }
    for (int i = tid; i < GQ_ * KP_; i += 128) {
        int gl = i / KP_, kk = i % KP_;
        float v = (kk < KK_) ? b2[(g0 + gl) * KK_ + kk] : 0.f;
        s_b2[i] = make_float2(v, v);
    }
    __syncthreads();

    const int b    = blockIdx.z;
    const int h    = blockIdx.y * 4 + threadIdx.y;
    const int lane = threadIdx.x;            // warp spans one full row
    const int w    = lane * 4;               // 4 pixels: two FFMA2 pairs

    const float* xb = x + (size_t)b * C_ * H_ * W_;

    // Load t for both pixel pairs: one LDG.128 per o, pre-packed pairs
    u64 tv0[O_], tv1[O_];
    {
        const u64* tp = reinterpret_cast<const u64*>(
            t_scratch + ((size_t)b * O_ * H_ + h) * W_ + w);
#pragma unroll
        for (int o = 0; o < O_; o++) {
            ulonglong2 v = *reinterpret_cast<const ulonglong2*>(
                tp + o * (H_ * W_ / 2));
            tv0[o] = v.x;   // (t[w],   t[w+1])
            tv1[o] = v.y;   // (t[w+2], t[w+3])
        }
    }

    const bool hv0 = (h > 0);
    const bool hv2 = (h < H_ - 1);
    const bool lv  = (lane > 0);     // left halo valid (lane0 = image edge)
    const bool rv  = (lane < 31);    // right halo valid

    float* outp = out + (size_t)b * C_ * H_ * W_ + h * W_ + w;

#pragma unroll 1
    for (int gl = 0; gl < GQ_; gl++) {
        u64 wk0[KK_], wk1[KK_];
        {
            const u64* brow = reinterpret_cast<const u64*>(s_b2) + gl * KP_;
            const ulonglong2* brow2 = reinterpret_cast<const ulonglong2*>(brow);
#pragma unroll
            for (int kp = 0; kp < 4; kp++) {
                ulonglong2 v = lds128(brow2 + kp);
                wk0[2 * kp + 0] = v.x;  wk1[2 * kp + 0] = v.x;
                wk0[2 * kp + 1] = v.y;  wk1[2 * kp + 1] = v.y;
            }
            wk0[8] = brow[8];  wk1[8] = brow[8];
        }

        // weight GEMV: each LDS feeds 2 FFMA2 (one per pixel pair)
#pragma unroll
        for (int o = 0; o < O_; o++) {
            u64 t0 = tv0[o], t1 = tv1[o];
            const u64* wrow =
                reinterpret_cast<const u64*>(&s_w2[(gl * O_ + o) * KP_]);
            const ulonglong2* wrow2 = reinterpret_cast<const ulonglong2*>(wrow);
#pragma unroll
            for (int kp = 0; kp < 4; kp++) {
                ulonglong2 v = lds128(wrow2 + kp);
                fma2(wk0[2 * kp + 0], t0, v.x);
                fma2(wk1[2 * kp + 0], t1, v.x);
                fma2(wk0[2 * kp + 1], t0, v.y);
                fma2(wk1[2 * kp + 1], t1, v.y);
            }
            u64 v8 = wrow[8];
            fma2(wk0[8], t0, v8);
            fma2(wk1[8], t1, v8);
        }

        // 3x3 gather, 4 pixels; halo via warp shuffle (warp = full row)
#pragma unroll
        for (int cc = 0; cc < GC_; cc++) {
            const int c = (g0 + gl) * GC_ + cc;
            const float* xr = xb + (size_t)c * (H_ * W_) + h * W_ + w;
            u64 a0A = 0ULL, a0B = 0ULL;   // pair0: two dep chains
            u64 a1A = 0ULL, a1B = 0ULL;   // pair1
#pragma unroll
            for (int di = 0; di < 3; di++) {
                const bool hv = (di == 0) ? hv0 : ((di == 2) ? hv2 : true);
                const float* row = xr + (di - 1) * W_;
                ulonglong2 m = hv ? *reinterpret_cast<const ulonglong2*>(row)
                                  : make_ulonglong2(0ULL, 0ULL);
                float m0, m1, m2, m3;
                unpack2(m.x, m0, m1);
                unpack2(m.y, m2, m3);
                // halo from neighbor lanes; image edge -> 0
                float L = __shfl_up_sync(0xffffffffu, m3, 1);
                float R = __shfl_down_sync(0xffffffffu, m0, 1);
                L = lv ? L : 0.f;
                R = rv ? R : 0.f;
                u64 pL  = pack2(L,  m0);
                u64 p12 = pack2(m1, m2);
                u64 p3R = pack2(m3, R);
                u64& acc0 = (di == 1) ? a0B : a0A;
                u64& acc1 = (di == 1) ? a1B : a1A;
                fma2(acc0, wk0[3 * di + 0], pL);
                fma2(acc0, wk0[3 * di + 1], m.x);
                fma2(acc0, wk0[3 * di + 2], p12);
                fma2(acc1, wk1[3 * di + 0], p12);
                fma2(acc1, wk1[3 * di + 1], m.y);
                fma2(acc1, wk1[3 * di + 2], p3R);
            }
            ulonglong2 res;
            res.x = add2(a0A, a0B);
            res.y = add2(a1A, a1B);
            *reinterpret_cast<ulonglong2*>(outp + (size_t)c * (H_ * W_)) = res;
        }
    }
}

extern "C" void kernel_launch(void* const* d_in, const int* in_sizes, int n_in,
                              void* d_out, int out_size)
{
    (void)in_sizes; (void)n_in; (void)out_size;
    const float* x  = (const float*)d_in[0];
    const float* w1 = (const float*)d_in[1];
    const float* b1 = (const float*)d_in[2];
    const float* pa = (const float*)d_in[3];
    const float* w2 = (const float*)d_in[4];
    const float* b2 = (const float*)d_in[5];
    float* out = (float*)d_out;

    // Kernel A: 1024 small CTAs (2 warps each)
    dim3 blockA(64, 1, 1);
    dim3 gridA(1, H_, B_);
    gen_t_kernel<<<gridA, blockA>>>(x, w1, b1, pa);

    // Kernel B: 1024 CTAs, 4-way group split, 4 px/thread
    dim3 blockB(32, 4, 1);
    dim3 gridB(4, H_ / 4, B_);
    involution_apply_kernel<<<gridB, blockB>>>(x, w2, b2, out);
}